// round 14
// baseline (speedup 1.0000x reference)
#include <cuda_runtime.h>
#include <cuda_fp16.h>
#include <stdint.h>

// ============================================================================
// CrossAttention collapses algebraically:
//   softmax over k sums to 1 per query -> sum over (q,k) of scores = L = 2048.
//   einsum 'bvhd,bhqk->bvhd' has no shared contraction index, so attn = v*2048:
//     out = 2048 * x @ (Wv@Wo) + (2048 * bv@Wo + bo)
// encoder_x / Wq / bq / Wk / bk are dead inputs.
//
// R14: x fp32->fp16 conversion moved to a FORKED STREAM captured into the
// graph (event fork/join), so it runs concurrently with gemm1 (which leaves
// DRAM idle). gemm1 = R12 (gemm+bias, 272 CTAs); gemm2 = R13 (all-fp16
// ldmatrix operands, measured 48.0us).
//   graph: [gemm1 || cvt_x] -> gemm2
// ============================================================================

// ---------------- scratch ----------------------------------------------------
__device__ __half g_xh  [8192u * 1024u];
__device__ __half g_WcTh[1024u * 1024u];
__device__ float  g_t[1024];

// ---------------- helpers ----------------------------------------------------
__device__ __forceinline__ uint32_t smem_u32(const void* p) {
    uint32_t a;
    asm("{ .reg .u64 t; cvta.to.shared.u64 t, %1; cvt.u32.u64 %0, t; }"
        : "=r"(a) : "l"(p));
    return a;
}
__device__ __forceinline__ void cp_async16(uint32_t saddr, const void* gaddr) {
    asm volatile("cp.async.cg.shared.global [%0], [%1], 16;"
                 :: "r"(saddr), "l"(gaddr));
}
#define CP_COMMIT() asm volatile("cp.async.commit_group;" ::: "memory")
#define CP_WAIT0()  asm volatile("cp.async.wait_group 0;" ::: "memory")

__device__ __forceinline__ void mma16816(float* c, const uint32_t* a,
                                         const uint32_t* b) {
    asm volatile(
        "mma.sync.aligned.m16n8k16.row.col.f32.f16.f16.f32 "
        "{%0,%1,%2,%3}, {%4,%5,%6,%7}, {%8,%9}, {%0,%1,%2,%3};"
        : "+f"(c[0]), "+f"(c[1]), "+f"(c[2]), "+f"(c[3])
        : "r"(a[0]), "r"(a[1]), "r"(a[2]), "r"(a[3]), "r"(b[0]), "r"(b[1]));
}
__device__ __forceinline__ void ldsm4(uint32_t* r, uint32_t addr) {
    asm volatile("ldmatrix.sync.aligned.m8n8.x4.shared.b16 {%0,%1,%2,%3}, [%4];"
                 : "=r"(r[0]), "=r"(r[1]), "=r"(r[2]), "=r"(r[3]) : "r"(addr));
}
// fp16 tile (128B rows): 16B-granule XOR swizzle
__device__ __forceinline__ uint32_t swzH(int row, int col) {
    return (uint32_t)(row * 128 + (col ^ ((row & 7) << 4)));
}
// fp32 tile (256B rows): 32B-granule XOR swizzle
__device__ __forceinline__ uint32_t swzF(int row, int col) {
    return (uint32_t)(row * 256 + (col ^ ((row & 7) << 5)));
}
__device__ __forceinline__ uint32_t h2u(__half2 h) {
    union { __half2 h; uint32_t u; } c; c.h = h; return c.u;
}
__device__ __forceinline__ uint32_t f2h2(float a, float b) {
    return h2u(__floats2half2_rn(a, b));
}

// ============================================================================
// cvt_x: x fp32 -> fp16  (runs on forked stream, concurrent with gemm1)
// grid 1024 x 256 threads, 8 float4 per thread.
// ============================================================================
__global__ __launch_bounds__(256)
void cvt_x(const float* __restrict__ x, __half* __restrict__ xh)
{
    const int base = blockIdx.x * 2048 + threadIdx.x;   // float4 units
    #pragma unroll
    for (int i = 0; i < 8; i++) {
        const int idx = base + i * 256;
        const float4 v = ((const float4*)x)[idx];
        ((__half2*)xh)[2 * idx]     = __floats2half2_rn(v.x, v.y);
        ((__half2*)xh)[2 * idx + 1] = __floats2half2_rn(v.z, v.w);
    }
}

// ============================================================================
// gemm1: WcT[m,n] = sum_k Wo[k,m] * Wv[n,k]   (fp32 in, fp16 out)
// BM=64, BN=64, BK=64.  4 warps, warp 32x32.  256 GEMM CTAs + 16 bias CTAs.
// ============================================================================
#define G1T 128
constexpr uint32_t G1_AT  = 64u * 272u;
constexpr uint32_t G1_BT  = 64u * 256u;
constexpr uint32_t G1_STG = G1_AT + G1_BT;
constexpr uint32_t SM_G1  = 2u * G1_STG;

__global__ __launch_bounds__(G1T)
void gemm1_w(const float* __restrict__ Wo, const float* __restrict__ Wv,
             __half* __restrict__ WcT,
             const float* __restrict__ bv, const float* __restrict__ bo,
             float* __restrict__ tvec)
{
    const int tid = threadIdx.x;

    if (blockIdx.y == 16) {     // ---- bias CTAs
        __shared__ float red[2][64];
        const int c = tid & 63, q = tid >> 6;
        const int j = blockIdx.x * 64 + c;
        const int i0 = q * 512;
        float s = 0.0f;
        #pragma unroll 16
        for (int i = 0; i < 512; i++)
            s = fmaf(bv[i0 + i], Wo[(size_t)(i0 + i) * 1024 + j], s);
        red[q][c] = s;
        __syncthreads();
        if (q == 0)
            tvec[j] = 2048.0f * (red[0][c] + red[1][c]) + bo[j];
        return;
    }

    extern __shared__ char smem[];
    const uint32_t sb = smem_u32(smem);
    const int wid = tid >> 5, lane = tid & 31;
    const int g = lane >> 2, tig = lane & 3;
    const int mb = blockIdx.y * 64;
    const int nb = blockIdx.x * 64;
    const int wm = (wid & 1) * 32;
    const int wn = (wid >> 1) * 32;

    float acc[2][4][4];
    #pragma unroll
    for (int mt = 0; mt < 2; mt++)
        #pragma unroll
        for (int nt = 0; nt < 4; nt++)
            #pragma unroll
            for (int i = 0; i < 4; i++) acc[mt][nt][i] = 0.0f;

    auto issue = [&](int c) {
        const int k0 = c * 64;
        const uint32_t stg = sb + (uint32_t)(c & 1) * G1_STG;
        #pragma unroll
        for (int i = 0; i < 8; i++) {          // A: Wo rows, 272B pitch
            const int li = i * G1T + tid;
            const int r = li >> 4, gc = li & 15;
            cp_async16(stg + (uint32_t)(r * 272 + gc * 16),
                       Wo + (size_t)(k0 + r) * 1024 + mb + gc * 4);
        }
        #pragma unroll
        for (int i = 0; i < 8; i++) {          // B: Wv rows, swzF
            const int li = i * G1T + tid;
            const int r = li >> 4, gc = li & 15;
            cp_async16(stg + G1_AT + swzF(r, gc * 16),
                       Wv + (size_t)(nb + r) * 1024 + k0 + gc * 4);
        }
        CP_COMMIT();
    };

    issue(0);

    for (int c = 0; c < 16; c++) {
        CP_WAIT0();
        __syncthreads();
        if (c + 1 < 16) issue(c + 1);

        const char* baseA = smem + (size_t)(c & 1) * G1_STG;
        const char* baseB = baseA + G1_AT;

        #pragma unroll
        for (int ks = 0; ks < 4; ks++) {
            const int ka = ks * 16 + tig * 2;
            uint32_t aF[2][4], bF[4][2];

            #pragma unroll
            for (int mt = 0; mt < 2; mt++) {
                const int m0 = wm + mt * 16 + g, m1 = m0 + 8;
                const char* r0p = baseA + ka * 272;
                const char* r1p = r0p + 272;
                const char* r8p = r0p + 8 * 272;
                const char* r9p = r8p + 272;
                aF[mt][0] = f2h2(*(const float*)(r0p + m0 * 4),
                                 *(const float*)(r1p + m0 * 4));
                aF[mt][1] = f2h2(*(const float*)(r0p + m1 * 4),
                                 *(const float*)(r1p + m1 * 4));
                aF[mt][2] = f2h2(*(const float*)(r8p + m0 * 4),
                                 *(const float*)(r9p + m0 * 4));
                aF[mt][3] = f2h2(*(const float*)(r8p + m1 * 4),
                                 *(const float*)(r9p + m1 * 4));
            }
            #pragma unroll
            for (int nt = 0; nt < 4; nt++) {
                const int row = wn + nt * 8 + g;
                const int cb = ka * 4;
                float2 lo = *(const float2*)(baseB + swzF(row, cb));
                float2 hi = *(const float2*)(baseB + swzF(row, cb + 32));
                bF[nt][0] = f2h2(lo.x, lo.y);
                bF[nt][1] = f2h2(hi.x, hi.y);
            }
            #pragma unroll
            for (int mt = 0; mt < 2; mt++)
                #pragma unroll
                for (int nt = 0; nt < 4; nt++)
                    mma16816(acc[mt][nt], aF[mt], bF[nt]);
        }
        __syncthreads();
    }

    #pragma unroll
    for (int mt = 0; mt < 2; mt++) {
        const size_t r0 = (size_t)mb + wm + mt * 16 + g;
        #pragma unroll
        for (int nt = 0; nt < 4; nt++) {
            const int c0 = nb + wn + nt * 8 + tig * 2;
            *(__half2*)(WcT + r0 * 1024 + c0) =
                __floats2half2_rn(acc[mt][nt][0], acc[mt][nt][1]);
            *(__half2*)(WcT + (r0 + 8) * 1024 + c0) =
                __floats2half2_rn(acc[mt][nt][2], acc[mt][nt][3]);
        }
    }
}

// ============================================================================
// gemm2: out[m,n] = 2048 * sum_k xh[m,k] * WcT[n,k] + t[n]
// BM=64, BN=128, 4 warps, warp tile 32x64, all-fp16 ldmatrix operands.
// 1024 CTAs, 3 CTAs/SM.  (R13, measured 48.0us.)
// ============================================================================
#define G2T 128
constexpr uint32_t G2_AT  = 64u * 128u;          // 8192  (fp16 A)
constexpr uint32_t G2_BT  = 128u * 128u;         // 16384 (fp16 B)
constexpr uint32_t G2_STG = G2_AT + G2_BT;       // 24576
constexpr uint32_t SM_G2  = 2u * G2_STG;         // 49152

__global__ __launch_bounds__(G2T, 3)
void gemm2_x(const __half* __restrict__ A, const __half* __restrict__ B,
             float* __restrict__ C, const float* __restrict__ bias)
{
    extern __shared__ char smem[];
    const uint32_t sb = smem_u32(smem);
    const int tid = threadIdx.x;
    const int wid = tid >> 5, lane = tid & 31;
    const int g = lane >> 2, tig = lane & 3;
    const int bm = blockIdx.y, bn = blockIdx.x;
    const int wm = (wid & 1) * 32;
    const int wn = (wid >> 1) * 64;
    const int lm = lane >> 3, lr = lane & 7;
    const int N = 1024, K = 1024;

    const __half* Ab = A + (size_t)bm * 64 * K;
    const __half* Bb = B + (size_t)bn * 128 * K;

    float acc[2][8][4];
    #pragma unroll
    for (int mt = 0; mt < 2; mt++)
        #pragma unroll
        for (int nt = 0; nt < 8; nt++)
            #pragma unroll
            for (int i = 0; i < 4; i++) acc[mt][nt][i] = 0.0f;

    auto issue = [&](int c) {
        const int k0 = c * 64;
        const uint32_t stg = sb + (uint32_t)(c & 1) * G2_STG;
        #pragma unroll
        for (int i = 0; i < 4; i++) {          // A: 64 rows x 8 granules
            const int li = i * G2T + tid;
            const int r = li >> 3, gc = li & 7;
            cp_async16(stg + swzH(r, gc * 16),
                       Ab + (size_t)r * K + k0 + gc * 8);
        }
        #pragma unroll
        for (int i = 0; i < 8; i++) {          // B: 128 rows x 8 granules
            const int li = i * G2T + tid;
            const int r = li >> 3, gc = li & 7;
            cp_async16(stg + G2_AT + swzH(r, gc * 16),
                       Bb + (size_t)r * K + k0 + gc * 8);
        }
        CP_COMMIT();
    };

    issue(0);

    for (int c = 0; c < 16; c++) {
        CP_WAIT0();
        __syncthreads();
        if (c + 1 < 16) issue(c + 1);

        const uint32_t tA = sb + (uint32_t)(c & 1) * G2_STG;
        const uint32_t tB = tA + G2_AT;

        #pragma unroll
        for (int ks = 0; ks < 4; ks++) {
            const int kb = ks * 32;
            uint32_t aF[2][4], bF[4][4];

            #pragma unroll
            for (int mt = 0; mt < 2; mt++) {
                const int row = wm + mt * 16 + (lm & 1) * 8 + lr;
                ldsm4(aF[mt], tA + swzH(row, kb + (lm >> 1) * 16));
            }
            #pragma unroll
            for (int nt2 = 0; nt2 < 4; nt2++) {
                const int row = wn + (2 * nt2 + (lm >> 1)) * 8 + lr;
                ldsm4(bF[nt2], tB + swzH(row, kb + (lm & 1) * 16));
            }
            #pragma unroll
            for (int mt = 0; mt < 2; mt++)
                #pragma unroll
                for (int nt2 = 0; nt2 < 4; nt2++) {
                    mma16816(acc[mt][2 * nt2],     aF[mt], &bF[nt2][0]);
                    mma16816(acc[mt][2 * nt2 + 1], aF[mt], &bF[nt2][2]);
                }
        }
        __syncthreads();
    }

    // ---- epilogue
    #pragma unroll
    for (int mt = 0; mt < 2; mt++) {
        const size_t r0 = (size_t)bm * 64 + wm + mt * 16 + g;
        #pragma unroll
        for (int nt = 0; nt < 8; nt++) {
            const int c0 = bn * 128 + wn + nt * 8 + tig * 2;
            const float bx = bias[c0], by = bias[c0 + 1];
            *(float2*)(C + r0 * N + c0) =
                make_float2(2048.0f * acc[mt][nt][0] + bx,
                            2048.0f * acc[mt][nt][1] + by);
            *(float2*)(C + (r0 + 8) * N + c0) =
                make_float2(2048.0f * acc[mt][nt][2] + bx,
                            2048.0f * acc[mt][nt][3] + by);
        }
    }
}

// ---------------------------------------------------------------------------
extern "C" void kernel_launch(void* const* d_in, const int* in_sizes, int n_in,
                              void* d_out, int out_size)
{
    const float* x  = (const float*)d_in[0];
    // d_in[1..5] = encoder_x, Wq, bq, Wk, bk -- mathematically dead
    const float* Wv = (const float*)d_in[6];
    const float* bv = (const float*)d_in[7];
    const float* Wo = (const float*)d_in[8];
    const float* bo = (const float*)d_in[9];
    float* out = (float*)d_out;

    __half *xh, *WcTh;
    float* t;
    cudaGetSymbolAddress((void**)&xh,   g_xh);
    cudaGetSymbolAddress((void**)&WcTh, g_WcTh);
    cudaGetSymbolAddress((void**)&t,    g_t);

    // one-time host-side resources (created on the uncaptured correctness
    // call; reused identically on every call -- work is deterministic)
    static cudaStream_t s2 = nullptr;
    static cudaEvent_t evFork = nullptr, evJoin = nullptr;
    if (!s2) {
        cudaStreamCreateWithFlags(&s2, cudaStreamNonBlocking);
        cudaEventCreateWithFlags(&evFork, cudaEventDisableTiming);
        cudaEventCreateWithFlags(&evJoin, cudaEventDisableTiming);
        cudaFuncSetAttribute(gemm1_w,
                             cudaFuncAttributeMaxDynamicSharedMemorySize, SM_G1);
        cudaFuncSetAttribute(gemm2_x,
                             cudaFuncAttributeMaxDynamicSharedMemorySize, SM_G2);
    }

    // fork: cvt_x runs concurrently with gemm1 on stream s2
    cudaEventRecord(evFork, 0);
    cudaStreamWaitEvent(s2, evFork, 0);
    cvt_x<<<1024, 256, 0, s2>>>(x, xh);
    cudaEventRecord(evJoin, s2);

    // gemm1 on the main stream: 256 GEMM CTAs + 16 bias CTAs
    {
        dim3 g(16, 17);
        gemm1_w<<<g, G1T, SM_G1>>>(Wo, Wv, WcTh, bv, bo, t);
    }

    // join, then gemm2
    cudaStreamWaitEvent(0, evJoin, 0);
    {
        dim3 g(8, 128);
        gemm2_x<<<g, G2T, SM_G2>>>(xh, WcTh, out, t);
    }
}

// round 15
// speedup vs baseline: 1.0256x; 1.0256x over previous
#include <cuda_runtime.h>
#include <cuda_fp16.h>
#include <stdint.h>

// ============================================================================
// CrossAttention collapses algebraically:
//   softmax over k sums to 1 per query -> sum over (q,k) of scores = L = 2048.
//   einsum 'bvhd,bhqk->bvhd' has no shared contraction index, so attn = v*2048:
//     out = 2048 * x @ (Wv@Wo) + (2048 * bv@Wo + bo)
// encoder_x / Wq / bq / Wk / bk are dead inputs.
//
// R15: single gemm1 launch fuses THREE jobs, ordered so the cheap DRAM-bound
// x-conversion CTAs come FIRST in blockIdx order (wave-1 co-residency with
// the tensor-bound gemm CTAs -> overlap, not trailing):
//   y in [0,32):  x fp32 -> fp16   (512 CTAs)
//   y == 32:      bias t = 2048*bv@Wo + bo  (16 CTAs)
//   y in [33,49): WcT = Wo^T @ Wv^T  (256 CTAs, 64x64 tiles)
// gemm2 = measured-best all-fp16 ldmatrix version (48.0us).
// ============================================================================

// ---------------- scratch ----------------------------------------------------
__device__ __half g_xh  [8192u * 1024u];
__device__ __half g_WcTh[1024u * 1024u];
__device__ float  g_t[1024];

// ---------------- helpers ----------------------------------------------------
__device__ __forceinline__ uint32_t smem_u32(const void* p) {
    uint32_t a;
    asm("{ .reg .u64 t; cvta.to.shared.u64 t, %1; cvt.u32.u64 %0, t; }"
        : "=r"(a) : "l"(p));
    return a;
}
__device__ __forceinline__ void cp_async16(uint32_t saddr, const void* gaddr) {
    asm volatile("cp.async.cg.shared.global [%0], [%1], 16;"
                 :: "r"(saddr), "l"(gaddr));
}
#define CP_COMMIT() asm volatile("cp.async.commit_group;" ::: "memory")
#define CP_WAIT0()  asm volatile("cp.async.wait_group 0;" ::: "memory")

__device__ __forceinline__ void mma16816(float* c, const uint32_t* a,
                                         const uint32_t* b) {
    asm volatile(
        "mma.sync.aligned.m16n8k16.row.col.f32.f16.f16.f32 "
        "{%0,%1,%2,%3}, {%4,%5,%6,%7}, {%8,%9}, {%0,%1,%2,%3};"
        : "+f"(c[0]), "+f"(c[1]), "+f"(c[2]), "+f"(c[3])
        : "r"(a[0]), "r"(a[1]), "r"(a[2]), "r"(a[3]), "r"(b[0]), "r"(b[1]));
}
__device__ __forceinline__ void ldsm4(uint32_t* r, uint32_t addr) {
    asm volatile("ldmatrix.sync.aligned.m8n8.x4.shared.b16 {%0,%1,%2,%3}, [%4];"
                 : "=r"(r[0]), "=r"(r[1]), "=r"(r[2]), "=r"(r[3]) : "r"(addr));
}
// fp16 tile (128B rows): 16B-granule XOR swizzle
__device__ __forceinline__ uint32_t swzH(int row, int col) {
    return (uint32_t)(row * 128 + (col ^ ((row & 7) << 4)));
}
// fp32 tile (256B rows): 32B-granule XOR swizzle
__device__ __forceinline__ uint32_t swzF(int row, int col) {
    return (uint32_t)(row * 256 + (col ^ ((row & 7) << 5)));
}
__device__ __forceinline__ uint32_t h2u(__half2 h) {
    union { __half2 h; uint32_t u; } c; c.h = h; return c.u;
}
__device__ __forceinline__ uint32_t f2h2(float a, float b) {
    return h2u(__floats2half2_rn(a, b));
}

// ============================================================================
// gemm1 fused launch (grid 16 x 49):
//   y<32: x cvt   y==32: bias   y>=33: 64x64 GEMM tiles
// ============================================================================
#define G1T 128
constexpr uint32_t G1_AT  = 64u * 272u;
constexpr uint32_t G1_BT  = 64u * 256u;
constexpr uint32_t G1_STG = G1_AT + G1_BT;
constexpr uint32_t SM_G1  = 2u * G1_STG;

__global__ __launch_bounds__(G1T)
void gemm1_w(const float* __restrict__ Wo, const float* __restrict__ Wv,
             const float* __restrict__ x, __half* __restrict__ xh,
             __half* __restrict__ WcT,
             const float* __restrict__ bv, const float* __restrict__ bo,
             float* __restrict__ tvec)
{
    const int tid = threadIdx.x;

    if (blockIdx.y < 32) {      // ---- x conversion CTAs (512, FIRST in order)
        const int cta = blockIdx.y * 16 + blockIdx.x;          // 0..511
        const int base = cta * 4096;                            // float4 units
        #pragma unroll 8
        for (int i = 0; i < 32; i++) {
            const int idx = base + i * G1T + tid;
            const float4 v = ((const float4*)x)[idx];
            ((__half2*)xh)[2 * idx]     = __floats2half2_rn(v.x, v.y);
            ((__half2*)xh)[2 * idx + 1] = __floats2half2_rn(v.z, v.w);
        }
        return;
    }

    if (blockIdx.y == 32) {     // ---- bias CTAs (16)
        __shared__ float red[2][64];
        const int c = tid & 63, q = tid >> 6;
        const int j = blockIdx.x * 64 + c;
        const int i0 = q * 512;
        float s = 0.0f;
        #pragma unroll 16
        for (int i = 0; i < 512; i++)
            s = fmaf(bv[i0 + i], Wo[(size_t)(i0 + i) * 1024 + j], s);
        red[q][c] = s;
        __syncthreads();
        if (q == 0)
            tvec[j] = 2048.0f * (red[0][c] + red[1][c]) + bo[j];
        return;
    }

    // ---- GEMM CTAs (256) ---------------------------------------------------
    extern __shared__ char smem[];
    const uint32_t sb = smem_u32(smem);
    const int wid = tid >> 5, lane = tid & 31;
    const int g = lane >> 2, tig = lane & 3;
    const int mb = (blockIdx.y - 33) * 64;
    const int nb = blockIdx.x * 64;
    const int wm = (wid & 1) * 32;
    const int wn = (wid >> 1) * 32;

    float acc[2][4][4];
    #pragma unroll
    for (int mt = 0; mt < 2; mt++)
        #pragma unroll
        for (int nt = 0; nt < 4; nt++)
            #pragma unroll
            for (int i = 0; i < 4; i++) acc[mt][nt][i] = 0.0f;

    auto issue = [&](int c) {
        const int k0 = c * 64;
        const uint32_t stg = sb + (uint32_t)(c & 1) * G1_STG;
        #pragma unroll
        for (int i = 0; i < 8; i++) {          // A: Wo rows, 272B pitch
            const int li = i * G1T + tid;
            const int r = li >> 4, gc = li & 15;
            cp_async16(stg + (uint32_t)(r * 272 + gc * 16),
                       Wo + (size_t)(k0 + r) * 1024 + mb + gc * 4);
        }
        #pragma unroll
        for (int i = 0; i < 8; i++) {          // B: Wv rows, swzF
            const int li = i * G1T + tid;
            const int r = li >> 4, gc = li & 15;
            cp_async16(stg + G1_AT + swzF(r, gc * 16),
                       Wv + (size_t)(nb + r) * 1024 + k0 + gc * 4);
        }
        CP_COMMIT();
    };

    issue(0);

    for (int c = 0; c < 16; c++) {
        CP_WAIT0();
        __syncthreads();
        if (c + 1 < 16) issue(c + 1);

        const char* baseA = smem + (size_t)(c & 1) * G1_STG;
        const char* baseB = baseA + G1_AT;

        #pragma unroll
        for (int ks = 0; ks < 4; ks++) {
            const int ka = ks * 16 + tig * 2;
            uint32_t aF[2][4], bF[4][2];

            #pragma unroll
            for (int mt = 0; mt < 2; mt++) {
                const int m0 = wm + mt * 16 + g, m1 = m0 + 8;
                const char* r0p = baseA + ka * 272;
                const char* r1p = r0p + 272;
                const char* r8p = r0p + 8 * 272;
                const char* r9p = r8p + 272;
                aF[mt][0] = f2h2(*(const float*)(r0p + m0 * 4),
                                 *(const float*)(r1p + m0 * 4));
                aF[mt][1] = f2h2(*(const float*)(r0p + m1 * 4),
                                 *(const float*)(r1p + m1 * 4));
                aF[mt][2] = f2h2(*(const float*)(r8p + m0 * 4),
                                 *(const float*)(r9p + m0 * 4));
                aF[mt][3] = f2h2(*(const float*)(r8p + m1 * 4),
                                 *(const float*)(r9p + m1 * 4));
            }
            #pragma unroll
            for (int nt = 0; nt < 4; nt++) {
                const int row = wn + nt * 8 + g;
                const int cb = ka * 4;
                float2 lo = *(const float2*)(baseB + swzF(row, cb));
                float2 hi = *(const float2*)(baseB + swzF(row, cb + 32));
                bF[nt][0] = f2h2(lo.x, lo.y);
                bF[nt][1] = f2h2(hi.x, hi.y);
            }
            #pragma unroll
            for (int mt = 0; mt < 2; mt++)
                #pragma unroll
                for (int nt = 0; nt < 4; nt++)
                    mma16816(acc[mt][nt], aF[mt], bF[nt]);
        }
        __syncthreads();
    }

    #pragma unroll
    for (int mt = 0; mt < 2; mt++) {
        const size_t r0 = (size_t)mb + wm + mt * 16 + g;
        #pragma unroll
        for (int nt = 0; nt < 4; nt++) {
            const int c0 = nb + wn + nt * 8 + tig * 2;
            *(__half2*)(WcT + r0 * 1024 + c0) =
                __floats2half2_rn(acc[mt][nt][0], acc[mt][nt][1]);
            *(__half2*)(WcT + (r0 + 8) * 1024 + c0) =
                __floats2half2_rn(acc[mt][nt][2], acc[mt][nt][3]);
        }
    }
}

// ============================================================================
// gemm2: out[m,n] = 2048 * sum_k xh[m,k] * WcT[n,k] + t[n]
// BM=64, BN=128, 4 warps, warp tile 32x64, all-fp16 ldmatrix operands.
// 1024 CTAs, 3 CTAs/SM.  (R13, measured 48.0us.)
// ============================================================================
#define G2T 128
constexpr uint32_t G2_AT  = 64u * 128u;          // 8192  (fp16 A)
constexpr uint32_t G2_BT  = 128u * 128u;         // 16384 (fp16 B)
constexpr uint32_t G2_STG = G2_AT + G2_BT;       // 24576
constexpr uint32_t SM_G2  = 2u * G2_STG;         // 49152

__global__ __launch_bounds__(G2T, 3)
void gemm2_x(const __half* __restrict__ A, const __half* __restrict__ B,
             float* __restrict__ C, const float* __restrict__ bias)
{
    extern __shared__ char smem[];
    const uint32_t sb = smem_u32(smem);
    const int tid = threadIdx.x;
    const int wid = tid >> 5, lane = tid & 31;
    const int g = lane >> 2, tig = lane & 3;
    const int bm = blockIdx.y, bn = blockIdx.x;
    const int wm = (wid & 1) * 32;
    const int wn = (wid >> 1) * 64;
    const int lm = lane >> 3, lr = lane & 7;
    const int N = 1024, K = 1024;

    const __half* Ab = A + (size_t)bm * 64 * K;
    const __half* Bb = B + (size_t)bn * 128 * K;

    float acc[2][8][4];
    #pragma unroll
    for (int mt = 0; mt < 2; mt++)
        #pragma unroll
        for (int nt = 0; nt < 8; nt++)
            #pragma unroll
            for (int i = 0; i < 4; i++) acc[mt][nt][i] = 0.0f;

    auto issue = [&](int c) {
        const int k0 = c * 64;
        const uint32_t stg = sb + (uint32_t)(c & 1) * G2_STG;
        #pragma unroll
        for (int i = 0; i < 4; i++) {          // A: 64 rows x 8 granules
            const int li = i * G2T + tid;
            const int r = li >> 3, gc = li & 7;
            cp_async16(stg + swzH(r, gc * 16),
                       Ab + (size_t)r * K + k0 + gc * 8);
        }
        #pragma unroll
        for (int i = 0; i < 8; i++) {          // B: 128 rows x 8 granules
            const int li = i * G2T + tid;
            const int r = li >> 3, gc = li & 7;
            cp_async16(stg + G2_AT + swzH(r, gc * 16),
                       Bb + (size_t)r * K + k0 + gc * 8);
        }
        CP_COMMIT();
    };

    issue(0);

    for (int c = 0; c < 16; c++) {
        CP_WAIT0();
        __syncthreads();
        if (c + 1 < 16) issue(c + 1);

        const uint32_t tA = sb + (uint32_t)(c & 1) * G2_STG;
        const uint32_t tB = tA + G2_AT;

        #pragma unroll
        for (int ks = 0; ks < 4; ks++) {
            const int kb = ks * 32;
            uint32_t aF[2][4], bF[4][4];

            #pragma unroll
            for (int mt = 0; mt < 2; mt++) {
                const int row = wm + mt * 16 + (lm & 1) * 8 + lr;
                ldsm4(aF[mt], tA + swzH(row, kb + (lm >> 1) * 16));
            }
            #pragma unroll
            for (int nt2 = 0; nt2 < 4; nt2++) {
                const int row = wn + (2 * nt2 + (lm >> 1)) * 8 + lr;
                ldsm4(bF[nt2], tB + swzH(row, kb + (lm & 1) * 16));
            }
            #pragma unroll
            for (int mt = 0; mt < 2; mt++)
                #pragma unroll
                for (int nt2 = 0; nt2 < 4; nt2++) {
                    mma16816(acc[mt][2 * nt2],     aF[mt], &bF[nt2][0]);
                    mma16816(acc[mt][2 * nt2 + 1], aF[mt], &bF[nt2][2]);
                }
        }
        __syncthreads();
    }

    // ---- epilogue
    #pragma unroll
    for (int mt = 0; mt < 2; mt++) {
        const size_t r0 = (size_t)bm * 64 + wm + mt * 16 + g;
        #pragma unroll
        for (int nt = 0; nt < 8; nt++) {
            const int c0 = bn * 128 + wn + nt * 8 + tig * 2;
            const float bx = bias[c0], by = bias[c0 + 1];
            *(float2*)(C + r0 * N + c0) =
                make_float2(2048.0f * acc[mt][nt][0] + bx,
                            2048.0f * acc[mt][nt][1] + by);
            *(float2*)(C + (r0 + 8) * N + c0) =
                make_float2(2048.0f * acc[mt][nt][2] + bx,
                            2048.0f * acc[mt][nt][3] + by);
        }
    }
}

// ---------------------------------------------------------------------------
extern "C" void kernel_launch(void* const* d_in, const int* in_sizes, int n_in,
                              void* d_out, int out_size)
{
    const float* x  = (const float*)d_in[0];
    // d_in[1..5] = encoder_x, Wq, bq, Wk, bk -- mathematically dead
    const float* Wv = (const float*)d_in[6];
    const float* bv = (const float*)d_in[7];
    const float* Wo = (const float*)d_in[8];
    const float* bo = (const float*)d_in[9];
    float* out = (float*)d_out;

    __half *xh, *WcTh;
    float* t;
    cudaGetSymbolAddress((void**)&xh,   g_xh);
    cudaGetSymbolAddress((void**)&WcTh, g_WcTh);
    cudaGetSymbolAddress((void**)&t,    g_t);

    static int smem_set = 0;
    if (!smem_set) {
        cudaFuncSetAttribute(gemm1_w,
                             cudaFuncAttributeMaxDynamicSharedMemorySize, SM_G1);
        cudaFuncSetAttribute(gemm2_x,
                             cudaFuncAttributeMaxDynamicSharedMemorySize, SM_G2);
        smem_set = 1;
    }

    // 1) fused launch: 512 x-cvt CTAs (first) + 16 bias + 256 GEMM
    {
        dim3 g(16, 49);   // y<32 cvt, y==32 bias, y>=33 gemm
        gemm1_w<<<g, G1T, SM_G1>>>(Wo, Wv, x, xh, WcTh, bv, bo, t);
    }

    // 2) gemm2: out = 2048 * xh @ Wc + t  (1024 CTAs, 4 warps, 3 CTAs/SM)
    {
        dim3 g(8, 128);
        gemm2_x<<<g, G2T, SM_G2>>>(xh, WcTh, out, t);
    }
}

// round 16
// speedup vs baseline: 1.0349x; 1.0090x over previous
#include <cuda_runtime.h>
#include <cuda_fp16.h>
#include <stdint.h>

// ============================================================================
// CrossAttention collapses algebraically:
//   softmax over k sums to 1 per query -> sum over (q,k) of scores = L = 2048.
//   einsum 'bvhd,bhqk->bvhd' has no shared contraction index, so attn = v*2048:
//     out = 2048 * x @ (Wv@Wo) + (2048 * bv@Wo + bo)
// encoder_x / Wq / bq / Wk / bk are dead inputs.
//
// R16: R12 structure (no x-cvt pass: gemm2 consumes fp32 x directly -- every
// attempt to overlap a standalone cvt failed; it serializes under capture).
// gemm1 re-tiled for latency hiding: same 64x64 CTA tile but 8 warps (warp
// tile 16x32) -> ~3.5 warps/SMSP (was 1.7). gemm2 = R12/R8 measured-best
// (64x128 CTA, 4 warps, 32x64 warp tile, fp32-A in-kernel cvt, 3 CTAs/SM).
// ============================================================================

// ---------------- scratch ----------------------------------------------------
__device__ __half g_WcTh[1024u * 1024u];
__device__ float  g_t[1024];

// ---------------- helpers ----------------------------------------------------
__device__ __forceinline__ uint32_t smem_u32(const void* p) {
    uint32_t a;
    asm("{ .reg .u64 t; cvta.to.shared.u64 t, %1; cvt.u32.u64 %0, t; }"
        : "=r"(a) : "l"(p));
    return a;
}
__device__ __forceinline__ void cp_async16(uint32_t saddr, const void* gaddr) {
    asm volatile("cp.async.cg.shared.global [%0], [%1], 16;"
                 :: "r"(saddr), "l"(gaddr));
}
#define CP_COMMIT() asm volatile("cp.async.commit_group;" ::: "memory")
#define CP_WAIT0()  asm volatile("cp.async.wait_group 0;" ::: "memory")

__device__ __forceinline__ void mma16816(float* c, const uint32_t* a,
                                         const uint32_t* b) {
    asm volatile(
        "mma.sync.aligned.m16n8k16.row.col.f32.f16.f16.f32 "
        "{%0,%1,%2,%3}, {%4,%5,%6,%7}, {%8,%9}, {%0,%1,%2,%3};"
        : "+f"(c[0]), "+f"(c[1]), "+f"(c[2]), "+f"(c[3])
        : "r"(a[0]), "r"(a[1]), "r"(a[2]), "r"(a[3]), "r"(b[0]), "r"(b[1]));
}
__device__ __forceinline__ void ldsm4(uint32_t* r, uint32_t addr) {
    asm volatile("ldmatrix.sync.aligned.m8n8.x4.shared.b16 {%0,%1,%2,%3}, [%4];"
                 : "=r"(r[0]), "=r"(r[1]), "=r"(r[2]), "=r"(r[3]) : "r"(addr));
}
// fp16 tile (128B rows): 16B-granule XOR swizzle
__device__ __forceinline__ uint32_t swzH(int row, int col) {
    return (uint32_t)(row * 128 + (col ^ ((row & 7) << 4)));
}
// fp32 tile (256B rows): 32B-granule XOR swizzle
__device__ __forceinline__ uint32_t swzF(int row, int col) {
    return (uint32_t)(row * 256 + (col ^ ((row & 7) << 5)));
}
__device__ __forceinline__ uint32_t h2u(__half2 h) {
    union { __half2 h; uint32_t u; } c; c.h = h; return c.u;
}
__device__ __forceinline__ uint32_t f2h2(float a, float b) {
    return h2u(__floats2half2_rn(a, b));
}

// ============================================================================
// gemm1: WcT[m,n] = sum_k Wo[k,m] * Wv[n,k]   (fp32 in, fp16 out)
// BM=64, BN=64, BK=64.  8 warps (256 thr), warp tile 16x32 (4 over m, 2 over n)
// -> ~3.5 warps/SMSP for gather-latency hiding.
// Bias CTAs (blockIdx.y == 16): t[j] = 2048*sum_i bv[i]*Wo[i,j] + bo[j].
// ============================================================================
#define G1T 256
constexpr uint32_t G1_AT  = 64u * 272u;
constexpr uint32_t G1_BT  = 64u * 256u;
constexpr uint32_t G1_STG = G1_AT + G1_BT;
constexpr uint32_t SM_G1  = 2u * G1_STG;

__global__ __launch_bounds__(G1T)
void gemm1_w(const float* __restrict__ Wo, const float* __restrict__ Wv,
             __half* __restrict__ WcT,
             const float* __restrict__ bv, const float* __restrict__ bo,
             float* __restrict__ tvec)
{
    const int tid = threadIdx.x;

    if (blockIdx.y == 16) {     // ---- bias CTAs (16)
        __shared__ float red[4][64];
        const int c = tid & 63, q = tid >> 6;     // q in 0..3
        const int j = blockIdx.x * 64 + c;
        const int i0 = q * 256;
        float s = 0.0f;
        #pragma unroll 16
        for (int i = 0; i < 256; i++)
            s = fmaf(bv[i0 + i], Wo[(size_t)(i0 + i) * 1024 + j], s);
        red[q][c] = s;
        __syncthreads();
        if (q == 0)
            tvec[j] = 2048.0f * (red[0][c] + red[1][c] +
                                 red[2][c] + red[3][c]) + bo[j];
        return;
    }

    // ---- GEMM CTAs (256) ---------------------------------------------------
    extern __shared__ char smem[];
    const uint32_t sb = smem_u32(smem);
    const int wid = tid >> 5, lane = tid & 31;
    const int g = lane >> 2, tig = lane & 3;
    const int mb = blockIdx.y * 64;
    const int nb = blockIdx.x * 64;
    const int wm = (wid >> 1) * 16;    // 4 warp-rows of 16
    const int wn = (wid & 1) * 32;     // 2 warp-cols of 32

    float acc[4][4];
    #pragma unroll
    for (int nt = 0; nt < 4; nt++)
        #pragma unroll
        for (int i = 0; i < 4; i++) acc[nt][i] = 0.0f;

    auto issue = [&](int c) {
        const int k0 = c * 64;
        const uint32_t stg = sb + (uint32_t)(c & 1) * G1_STG;
        #pragma unroll
        for (int i = 0; i < 4; i++) {          // A: Wo rows, 272B pitch
            const int li = i * G1T + tid;
            const int r = li >> 4, gc = li & 15;
            cp_async16(stg + (uint32_t)(r * 272 + gc * 16),
                       Wo + (size_t)(k0 + r) * 1024 + mb + gc * 4);
        }
        #pragma unroll
        for (int i = 0; i < 4; i++) {          // B: Wv rows, swzF
            const int li = i * G1T + tid;
            const int r = li >> 4, gc = li & 15;
            cp_async16(stg + G1_AT + swzF(r, gc * 16),
                       Wv + (size_t)(nb + r) * 1024 + k0 + gc * 4);
        }
        CP_COMMIT();
    };

    issue(0);

    for (int c = 0; c < 16; c++) {
        CP_WAIT0();
        __syncthreads();
        if (c + 1 < 16) issue(c + 1);

        const char* baseA = smem + (size_t)(c & 1) * G1_STG;
        const char* baseB = baseA + G1_AT;

        #pragma unroll
        for (int ks = 0; ks < 4; ks++) {
            const int ka = ks * 16 + tig * 2;
            uint32_t aF[4], bF[4][2];

            // A fragment (one 16-row m-tile): A[m,k] = tile[k-k0][m-mb]
            {
                const int m0 = wm + g, m1 = m0 + 8;
                const char* r0p = baseA + ka * 272;
                const char* r1p = r0p + 272;
                const char* r8p = r0p + 8 * 272;
                const char* r9p = r8p + 272;
                aF[0] = f2h2(*(const float*)(r0p + m0 * 4),
                             *(const float*)(r1p + m0 * 4));
                aF[1] = f2h2(*(const float*)(r0p + m1 * 4),
                             *(const float*)(r1p + m1 * 4));
                aF[2] = f2h2(*(const float*)(r8p + m0 * 4),
                             *(const float*)(r9p + m0 * 4));
                aF[3] = f2h2(*(const float*)(r8p + m1 * 4),
                             *(const float*)(r9p + m1 * 4));
            }
            // B fragments: 4 n-tiles of 8
            #pragma unroll
            for (int nt = 0; nt < 4; nt++) {
                const int row = wn + nt * 8 + g;
                const int cb = ka * 4;
                float2 lo = *(const float2*)(baseB + swzF(row, cb));
                float2 hi = *(const float2*)(baseB + swzF(row, cb + 32));
                bF[nt][0] = f2h2(lo.x, lo.y);
                bF[nt][1] = f2h2(hi.x, hi.y);
            }
            #pragma unroll
            for (int nt = 0; nt < 4; nt++)
                mma16816(acc[nt], aF, bF[nt]);
        }
        __syncthreads();
    }

    // ---- epilogue: fp16 half2 stores
    {
        const size_t r0 = (size_t)mb + wm + g;
        #pragma unroll
        for (int nt = 0; nt < 4; nt++) {
            const int c0 = nb + wn + nt * 8 + tig * 2;
            *(__half2*)(WcT + r0 * 1024 + c0) =
                __floats2half2_rn(acc[nt][0], acc[nt][1]);
            *(__half2*)(WcT + (r0 + 8) * 1024 + c0) =
                __floats2half2_rn(acc[nt][2], acc[nt][3]);
        }
    }
}

// ============================================================================
// gemm2: out[m,n] = 2048 * sum_k x[m,k] * WcT[n,k] + t[n]
// R12/R8 measured-best: BM=64, BN=128, 4 warps, warp tile 32x64.
// A = x fp32 (256B swzF rows, in-kernel cvt); B = WcT fp16 (swzH + ldmatrix).
// 1024 CTAs, 3 CTAs/SM.
// ============================================================================
#define G2T 128
constexpr uint32_t G2_AT  = 64u * 256u;          // 16384
constexpr uint32_t G2_BT  = 128u * 128u;         // 16384
constexpr uint32_t G2_STG = G2_AT + G2_BT;       // 32768
constexpr uint32_t SM_G2  = 2u * G2_STG;         // 65536

__global__ __launch_bounds__(G2T, 3)
void gemm2_x(const float* __restrict__ x, const __half* __restrict__ B,
             float* __restrict__ C, const float* __restrict__ bias)
{
    extern __shared__ char smem[];
    const uint32_t sb = smem_u32(smem);
    const int tid = threadIdx.x;
    const int wid = tid >> 5, lane = tid & 31;
    const int g = lane >> 2, tig = lane & 3;
    const int bm = blockIdx.y, bn = blockIdx.x;
    const int wm = (wid & 1) * 32;
    const int wn = (wid >> 1) * 64;
    const int lm = lane >> 3, lr = lane & 7;
    const int N = 1024, K = 1024;

    const float* Ab = x + (size_t)bm * 64 * K;
    const __half* Bb = B + (size_t)bn * 128 * K;

    float acc[2][8][4];
    #pragma unroll
    for (int mt = 0; mt < 2; mt++)
        #pragma unroll
        for (int nt = 0; nt < 8; nt++)
            #pragma unroll
            for (int i = 0; i < 4; i++) acc[mt][nt][i] = 0.0f;

    auto issue = [&](int c) {
        const int k0 = c * 64;
        const uint32_t stg = sb + (uint32_t)(c & 1) * G2_STG;
        #pragma unroll
        for (int i = 0; i < 8; i++) {          // A: 64 rows x 16 granules
            const int li = i * G2T + tid;
            const int r = li >> 4, gc = li & 15;
            cp_async16(stg + swzF(r, gc * 16),
                       Ab + (size_t)r * K + k0 + gc * 4);
        }
        #pragma unroll
        for (int i = 0; i < 8; i++) {          // B: 128 rows x 8 granules
            const int li = i * G2T + tid;
            const int r = li >> 3, gc = li & 7;
            cp_async16(stg + G2_AT + swzH(r, gc * 16),
                       Bb + (size_t)r * K + k0 + gc * 8);
        }
        CP_COMMIT();
    };

    issue(0);

    for (int c = 0; c < 16; c++) {
        CP_WAIT0();
        __syncthreads();
        if (c + 1 < 16) issue(c + 1);

        const char* baseA = smem + (size_t)(c & 1) * G2_STG;
        const uint32_t tB = sb + (uint32_t)(c & 1) * G2_STG + G2_AT;

        #pragma unroll
        for (int ks = 0; ks < 4; ks++) {
            const int kb = ks * 32;                 // fp16-tile byte col
            uint32_t aF[2][4], bF[4][4];

            // B first: ldmatrix chain issues under A's LDS/CVT chain
            #pragma unroll
            for (int nt2 = 0; nt2 < 4; nt2++) {
                const int row = wn + (2 * nt2 + (lm >> 1)) * 8 + lr;
                ldsm4(bF[nt2], tB + swzH(row, kb + (lm & 1) * 16));
            }
            const int cb = ks * 64 + tig * 8;       // fp32-tile byte col
            #pragma unroll
            for (int mt = 0; mt < 2; mt++) {
                const int r0 = wm + mt * 16 + g, r1 = r0 + 8;
                float2 v00 = *(const float2*)(baseA + swzF(r0, cb));
                float2 v10 = *(const float2*)(baseA + swzF(r1, cb));
                float2 v01 = *(const float2*)(baseA + swzF(r0, cb + 32));
                float2 v11 = *(const float2*)(baseA + swzF(r1, cb + 32));
                aF[mt][0] = f2h2(v00.x, v00.y);
                aF[mt][1] = f2h2(v10.x, v10.y);
                aF[mt][2] = f2h2(v01.x, v01.y);
                aF[mt][3] = f2h2(v11.x, v11.y);
            }
            #pragma unroll
            for (int mt = 0; mt < 2; mt++)
                #pragma unroll
                for (int nt2 = 0; nt2 < 4; nt2++) {
                    mma16816(acc[mt][2 * nt2],     aF[mt], &bF[nt2][0]);
                    mma16816(acc[mt][2 * nt2 + 1], aF[mt], &bF[nt2][2]);
                }
        }
        __syncthreads();
    }

    // ---- epilogue
    #pragma unroll
    for (int mt = 0; mt < 2; mt++) {
        const size_t r0 = (size_t)bm * 64 + wm + mt * 16 + g;
        #pragma unroll
        for (int nt = 0; nt < 8; nt++) {
            const int c0 = bn * 128 + wn + nt * 8 + tig * 2;
            const float bx = bias[c0], by = bias[c0 + 1];
            *(float2*)(C + r0 * N + c0) =
                make_float2(2048.0f * acc[mt][nt][0] + bx,
                            2048.0f * acc[mt][nt][1] + by);
            *(float2*)(C + (r0 + 8) * N + c0) =
                make_float2(2048.0f * acc[mt][nt][2] + bx,
                            2048.0f * acc[mt][nt][3] + by);
        }
    }
}

// ---------------------------------------------------------------------------
extern "C" void kernel_launch(void* const* d_in, const int* in_sizes, int n_in,
                              void* d_out, int out_size)
{
    const float* x  = (const float*)d_in[0];
    // d_in[1..5] = encoder_x, Wq, bq, Wk, bk -- mathematically dead
    const float* Wv = (const float*)d_in[6];
    const float* bv = (const float*)d_in[7];
    const float* Wo = (const float*)d_in[8];
    const float* bo = (const float*)d_in[9];
    float* out = (float*)d_out;

    __half* WcTh;
    float* t;
    cudaGetSymbolAddress((void**)&WcTh, g_WcTh);
    cudaGetSymbolAddress((void**)&t,    g_t);

    static int smem_set = 0;
    if (!smem_set) {
        cudaFuncSetAttribute(gemm1_w,
                             cudaFuncAttributeMaxDynamicSharedMemorySize, SM_G1);
        cudaFuncSetAttribute(gemm2_x,
                             cudaFuncAttributeMaxDynamicSharedMemorySize, SM_G2);
        smem_set = 1;
    }

    // 1) gemm1: WcT = Wo^T @ Wv^T  (256 CTAs, 8 warps) + 16 bias CTAs
    {
        dim3 g(16, 17);   // y==16 -> bias CTAs
        gemm1_w<<<g, G1T, SM_G1>>>(Wo, Wv, WcTh, bv, bo, t);
    }

    // 2) gemm2: out = 2048 * x @ Wc + t  (1024 CTAs, 4 warps, 3 CTAs/SM)
    {
        dim3 g(8, 128);
        gemm2_x<<<g, G2T, SM_G2>>>(x, WcTh, out, t);
    }
}